// round 6
// baseline (speedup 1.0000x reference)
#include <cuda_runtime.h>
#include <cuda_bf16.h>

#define N_NODES_MAX 1000000
#define KE_HALF 7.199822675975274f   // 14.399645351950548 / 2

// Per-node z value (index_to_z[species[i]], values 1..100 fit in u8).
// 1 MB; with streams bypassing L1 (ld.cv), this is the ONLY L1 content -> ~22% hit.
__device__ unsigned char g_z[N_NODES_MAX];
// a0*d..a3*d, c0..c3 (normalized), p
__device__ float g_params[9];

__device__ __forceinline__ float softplus_f(float x) {
    return log1pf(expf(x));
}

__global__ void prep_kernel(const int* __restrict__ species,
                            const int* __restrict__ index_to_z,
                            const float* __restrict__ a_raw,
                            const float* __restrict__ c_raw,
                            const float* __restrict__ p_raw,
                            const float* __restrict__ d_raw,
                            float* __restrict__ out,
                            int n_nodes) {
    int i = blockIdx.x * blockDim.x + threadIdx.x;

    if (i < 9) {
        float d = softplus_f(d_raw[0]);
        if (i < 4) {
            g_params[i] = softplus_f(a_raw[i]) * d;     // fold d into a_k
        } else if (i < 8) {
            float c0 = softplus_f(c_raw[0]);
            float c1 = softplus_f(c_raw[1]);
            float c2 = softplus_f(c_raw[2]);
            float c3 = softplus_f(c_raw[3]);
            float inv_s = 1.0f / (c0 + c1 + c2 + c3);
            g_params[i] = softplus_f(c_raw[i - 4]) * inv_s;
        } else {
            g_params[8] = softplus_f(p_raw[0]);         // p
        }
    }

    if (i < n_nodes) {
        out[i] = 0.0f;  // zero-init accumulator (harness poisons d_out)
        g_z[i] = (unsigned char)index_to_z[species[i]];
    }
}

// Full per-edge energy from z values (all math, no memory).
__device__ __forceinline__ float edge_compute(float dd, float cc,
                                              float zi, float zj,
                                              float a0, float a1, float a2, float a3,
                                              float c0, float c1, float c2, float c3,
                                              float p) {
    // z^p via exp(p*log z); z >= 1 so log is safe
    float zpi = __expf(p * __logf(zi));
    float zpj = __expf(p * __logf(zj));

    // x = (KE/2) * cutoff * z_i * z_j / (dist + 1e-8)
    float x = __fdividef(KE_HALF * cc * zi * zj, dd + 1e-8f);

    // t = dist * (zi^p + zj^p); a_k already scaled by d
    float t = dd * (zpi + zpj);

    float y = c0 * __expf(-a0 * t)
            + c1 * __expf(-a1 * t)
            + c2 * __expf(-a2 * t)
            + c3 * __expf(-a3 * t);

    // switch: w = 1 / (1 + exp(1/s1 - 1/sd)),  sd = d/1.5, s1 = 1 - d/1.5
    float sd = dd * (1.0f / 1.5f);
    float s1 = 1.0f - sd;
    sd = fmaxf(sd, 1e-8f);
    s1 = fmaxf(s1, 1e-8f);
    float e = __expf(__fdividef(1.0f, s1) - __fdividef(1.0f, sd));
    float w = __fdividef(1.0f, 1.0f + e);

    return w * x * y;
}

// L1-bypassing vector loads (ld.global.cv): streams never allocate in L1,
// so the z-table owns the full 228 KB L1D.
__device__ __forceinline__ float4 ldcv_f4(const float4* p) {
    float4 v;
    asm volatile("ld.global.cv.v4.f32 {%0,%1,%2,%3}, [%4];"
                 : "=f"(v.x), "=f"(v.y), "=f"(v.z), "=f"(v.w) : "l"(p));
    return v;
}
__device__ __forceinline__ int4 ldcv_i4(const int4* p) {
    int4 v;
    asm volatile("ld.global.cv.v4.b32 {%0,%1,%2,%3}, [%4];"
                 : "=r"(v.x), "=r"(v.y), "=r"(v.z), "=r"(v.w) : "l"(p));
    return v;
}

__global__ __launch_bounds__(256)
void edge_kernel(const float4* __restrict__ dist4,
                 const float4* __restrict__ cut4,
                 const int4* __restrict__ snd4,
                 const int4* __restrict__ rcv4,
                 float* __restrict__ out,
                 int n4, int n_tail_base, int n_edges) {
    int i = blockIdx.x * blockDim.x + threadIdx.x;

    float a0 = g_params[0], a1 = g_params[1], a2 = g_params[2], a3 = g_params[3];
    float c0 = g_params[4], c1 = g_params[5], c2 = g_params[6], c3 = g_params[7];
    float p  = g_params[8];

    if (i < n4) {
        float4 dv = ldcv_f4(&dist4[i]);
        float4 cv = ldcv_f4(&cut4[i]);
        int4   sv = ldcv_i4(&snd4[i]);
        int4   rv = ldcv_i4(&rcv4[i]);

        // 8 random u8 gathers, back-to-back (L1-resident table -> ~22% hit)
        float zj0 = (float)g_z[sv.x];
        float zj1 = (float)g_z[sv.y];
        float zj2 = (float)g_z[sv.z];
        float zj3 = (float)g_z[sv.w];
        float zi0 = (float)g_z[rv.x];
        float zi1 = (float)g_z[rv.y];
        float zi2 = (float)g_z[rv.z];
        float zi3 = (float)g_z[rv.w];

        float e0 = edge_compute(dv.x, cv.x, zi0, zj0, a0,a1,a2,a3, c0,c1,c2,c3, p);
        float e1 = edge_compute(dv.y, cv.y, zi1, zj1, a0,a1,a2,a3, c0,c1,c2,c3, p);
        float e2 = edge_compute(dv.z, cv.z, zi2, zj2, a0,a1,a2,a3, c0,c1,c2,c3, p);
        float e3 = edge_compute(dv.w, cv.w, zi3, zj3, a0,a1,a2,a3, c0,c1,c2,c3, p);

        atomicAdd(&out[rv.x], e0);
        atomicAdd(&out[rv.y], e1);
        atomicAdd(&out[rv.z], e2);
        atomicAdd(&out[rv.w], e3);
    }

    // tail (n_edges not divisible by 4): distribute over first warp's threads
    {
        int t = n_tail_base + i;
        if (t < n_edges && i < 32) {
            const float* dist = (const float*)dist4;
            const float* cut  = (const float*)cut4;
            const int*   snd  = (const int*)snd4;
            const int*   rcv  = (const int*)rcv4;
            float zi = (float)g_z[rcv[t]];
            float zj = (float)g_z[snd[t]];
            float en = edge_compute(dist[t], cut[t], zi, zj, a0,a1,a2,a3, c0,c1,c2,c3, p);
            atomicAdd(&out[rcv[t]], en);
        }
    }
}

extern "C" void kernel_launch(void* const* d_in, const int* in_sizes, int n_in,
                              void* d_out, int out_size) {
    const int*   node_species = (const int*)d_in[0];
    const float* distances    = (const float*)d_in[1];
    const float* cutoffs      = (const float*)d_in[2];
    const int*   senders      = (const int*)d_in[3];
    const int*   receivers    = (const int*)d_in[4];
    const int*   index_to_z   = (const int*)d_in[5];
    const float* a_raw        = (const float*)d_in[6];
    const float* c_raw        = (const float*)d_in[7];
    const float* p_raw        = (const float*)d_in[8];
    const float* d_raw        = (const float*)d_in[9];
    float* out = (float*)d_out;

    int n_nodes = in_sizes[0];
    int n_edges = in_sizes[1];

    {
        int threads = 256;
        int blocks = (n_nodes + threads - 1) / threads;
        prep_kernel<<<blocks, threads>>>(node_species, index_to_z,
                                         a_raw, c_raw, p_raw, d_raw,
                                         out, n_nodes);
    }
    {
        int n4 = n_edges >> 2;
        int threads = 256;
        int blocks = (n4 + threads - 1) / threads;
        if (blocks == 0) blocks = 1;
        edge_kernel<<<blocks, threads>>>((const float4*)distances,
                                         (const float4*)cutoffs,
                                         (const int4*)senders,
                                         (const int4*)receivers,
                                         out, n4, n4 << 2, n_edges);
    }
}